// round 12
// baseline (speedup 1.0000x reference)
#include <cuda_runtime.h>
#include <math.h>

// FINAL — Row-normalize: out[r, c] = in[r, c] / sum_c in[r, c]
// adj: [2, 32, 1024, 1024] fp32 -> 65536 rows of 1024 floats.
//
// Design (each element verified against ncu on GB300 across 11 rounds):
//  * One WARP per row: no __syncthreads, no smem round-trip (90.2 -> 82.0 us)
//  * 8 front-batched LDG.E.128.CS per lane (MLP=8 keeps L1tex queue full)
//  * Streaming .cs on both paths (read-once/write-once data; keep L2 clean)
//  * Scale in registers, 8x STG.E.128.CS
//
// Sits at the measured B300 LTS/DRAM ceiling (~6.5 TB/s combined) for a 1:1
// read/write stream. Falsified alternatives (all neutral or worse):
// block-reduce CTA-per-row, cp.async smem staging, 256-bit v8 accesses,
// persistent double-buffered pipeline, 128-thread CTAs, default cache policy.

static constexpr int ROW_LEN     = 1024;
static constexpr int V4_PER_ROW  = ROW_LEN / 4;     // 256 float4 per row
static constexpr int V4_PER_LANE = V4_PER_ROW / 32; // 8 float4 per lane
static constexpr int THREADS     = 256;             // 8 warps per CTA
static constexpr int WARPS       = THREADS / 32;

__global__ __launch_bounds__(THREADS)
void normalizer_kernel(const float* __restrict__ in, float* __restrict__ out) {
    const int lane = threadIdx.x & 31;
    const int wid  = threadIdx.x >> 5;
    const long long row   = (long long)blockIdx.x * WARPS + wid;  // 0 .. 65535
    const long long base4 = row * V4_PER_ROW;

    const float4* in4  = reinterpret_cast<const float4*>(in)  + base4 + lane;
    float4*       out4 = reinterpret_cast<float4*>(out)       + base4 + lane;

    // Front-batched streaming loads: 8 independent LDG.E.128.CS in flight.
    float4 v[V4_PER_LANE];
    #pragma unroll
    for (int i = 0; i < V4_PER_LANE; i++)
        v[i] = __ldcs(in4 + i * 32);

    // Per-lane partial sum (paired adds shorten the dependency chain)
    float s = 0.0f;
    #pragma unroll
    for (int i = 0; i < V4_PER_LANE; i++)
        s += (v[i].x + v[i].y) + (v[i].z + v[i].w);

    // Warp reduce (full warp participates; no barriers anywhere)
    #pragma unroll
    for (int off = 16; off > 0; off >>= 1)
        s += __shfl_xor_sync(0xFFFFFFFFu, s, off);

    // inv-degree with nan/inf guard (matches reference remove_nan_inf)
    float inv = 1.0f / s;
    inv = isfinite(inv) ? inv : 0.0f;

    // Scale in registers + streaming 128-bit stores.
    #pragma unroll
    for (int i = 0; i < V4_PER_LANE; i++) {
        float4 r;
        r.x = v[i].x * inv;
        r.y = v[i].y * inv;
        r.z = v[i].z * inv;
        r.w = v[i].w * inv;
        __stcs(out4 + i * 32, r);
    }
}

extern "C" void kernel_launch(void* const* d_in, const int* in_sizes, int n_in,
                              void* d_out, int out_size) {
    const float* adj = (const float*)d_in[0];
    float* out = (float*)d_out;
    const long long total = (long long)in_sizes[0];      // 2*32*1024*1024
    const int n_rows = (int)(total / ROW_LEN);            // 65536
    const int n_blocks = n_rows / WARPS;                  // 8192
    normalizer_kernel<<<n_blocks, THREADS>>>(adj, out);
}

// round 14
// speedup vs baseline: 1.0035x; 1.0035x over previous
#include <cuda_runtime.h>
#include <math.h>

// FINAL — Row-normalize: out[r, c] = in[r, c] / sum_c in[r, c]
// adj: [2, 32, 1024, 1024] fp32 -> 65536 rows of 1024 floats.
//
// Design (each element verified against ncu on GB300 across 12 rounds):
//  * One WARP per row: no __syncthreads, no smem round-trip (90.2 -> 82.0 us)
//  * 8 front-batched LDG.E.128.CS per lane (MLP=8 keeps L1tex queue full)
//  * Streaming .cs on both paths (read-once/write-once data; keep L2 clean)
//  * Scale in registers, 8x STG.E.128.CS
//
// Sits at the measured B300 LTS/DRAM ceiling (~6.5 TB/s combined) for a 1:1
// read/write stream. Falsified alternatives (all neutral or worse):
// block-reduce CTA-per-row, cp.async smem staging, 256-bit v8 accesses,
// persistent double-buffered pipeline, 128-thread CTAs, default cache policy.

static constexpr int ROW_LEN     = 1024;
static constexpr int V4_PER_ROW  = ROW_LEN / 4;     // 256 float4 per row
static constexpr int V4_PER_LANE = V4_PER_ROW / 32; // 8 float4 per lane
static constexpr int THREADS     = 256;             // 8 warps per CTA
static constexpr int WARPS       = THREADS / 32;

__global__ __launch_bounds__(THREADS)
void normalizer_kernel(const float* __restrict__ in, float* __restrict__ out) {
    const int lane = threadIdx.x & 31;
    const int wid  = threadIdx.x >> 5;
    const long long row   = (long long)blockIdx.x * WARPS + wid;  // 0 .. 65535
    const long long base4 = row * V4_PER_ROW;

    const float4* in4  = reinterpret_cast<const float4*>(in)  + base4 + lane;
    float4*       out4 = reinterpret_cast<float4*>(out)       + base4 + lane;

    // Front-batched streaming loads: 8 independent LDG.E.128.CS in flight.
    float4 v[V4_PER_LANE];
    #pragma unroll
    for (int i = 0; i < V4_PER_LANE; i++)
        v[i] = __ldcs(in4 + i * 32);

    // Per-lane partial sum (paired adds shorten the dependency chain)
    float s = 0.0f;
    #pragma unroll
    for (int i = 0; i < V4_PER_LANE; i++)
        s += (v[i].x + v[i].y) + (v[i].z + v[i].w);

    // Warp reduce (full warp participates; no barriers anywhere)
    #pragma unroll
    for (int off = 16; off > 0; off >>= 1)
        s += __shfl_xor_sync(0xFFFFFFFFu, s, off);

    // inv-degree with nan/inf guard (matches reference remove_nan_inf)
    float inv = 1.0f / s;
    inv = isfinite(inv) ? inv : 0.0f;

    // Scale in registers + streaming 128-bit stores.
    #pragma unroll
    for (int i = 0; i < V4_PER_LANE; i++) {
        float4 r;
        r.x = v[i].x * inv;
        r.y = v[i].y * inv;
        r.z = v[i].z * inv;
        r.w = v[i].w * inv;
        __stcs(out4 + i * 32, r);
    }
}

extern "C" void kernel_launch(void* const* d_in, const int* in_sizes, int n_in,
                              void* d_out, int out_size) {
    const float* adj = (const float*)d_in[0];
    float* out = (float*)d_out;
    const long long total = (long long)in_sizes[0];      // 2*32*1024*1024
    const int n_rows = (int)(total / ROW_LEN);            // 65536
    const int n_blocks = n_rows / WARPS;                  // 8192
    normalizer_kernel<<<n_blocks, THREADS>>>(adj, out);
}